// round 16
// baseline (speedup 1.0000x reference)
#include <cuda_runtime.h>
#include <math.h>

#define NL 6
#define B  8
#define T  4
#define L  2048
#define H  16
#define D  64
#define E  1024
#define FF 4096
#define INDIM 32
#define NTOK 32
#define DEPTH 3

#define CACHE_F4 50331648LL

#define GDW() asm volatile("griddepcontrol.wait;" ::: "memory")

__device__ __align__(16) float g_x   [NTOK * E];
__device__ __align__(16) float g_xn  [NTOK * E];
__device__ __align__(16) float g_attn[NTOK * E];
__device__ __align__(16) float g_seq [NTOK * INDIM];
__device__ __align__(16) float g_part[524288];    // [0,262144): qkv/l1; [262144,524288): op/l2

__device__ __forceinline__ unsigned long long pk2(float lo, float hi) {
    unsigned long long r;
    asm("mov.b64 %0, {%1, %2};" : "=l"(r) : "f"(lo), "f"(hi));
    return r;
}
__device__ __forceinline__ void fma2(unsigned long long& d,
                                     unsigned long long a,
                                     unsigned long long b) {
    asm("fma.rn.f32x2 %0, %1, %2, %3;" : "=l"(d) : "l"(a), "l"(b), "l"(d));
}
__device__ __forceinline__ float2 upk(unsigned long long v) {
    float2 f;
    asm("mov.b64 {%0, %1}, %2;" : "=f"(f.x), "=f"(f.y) : "l"(v));
    return f;
}
__device__ __forceinline__ void cpa16(unsigned dst, const void* src) {
    asm volatile("cp.async.ca.shared.global [%0], [%1], 16;" :: "r"(dst), "l"(src));
}
#define CP_COMMIT() asm volatile("cp.async.commit_group;")
#define CP_WAIT1()  asm volatile("cp.async.wait_group 1;")
__device__ __forceinline__ float gelu1(float v) {
    return 0.5f * v * (1.0f + erff(v * 0.70710678118654752f));
}

__global__ void cache_copy_kernel(const float4* __restrict__ in,
                                  float4* __restrict__ out, long n)
{
    long i = (long)blockIdx.x * blockDim.x + threadIdx.x;
    if (i < n) {
        float4 v = in[i];
        v.x = isnan(v.x) ? 0.0f : v.x;
        v.y = isnan(v.y) ? 0.0f : v.y;
        v.z = isnan(v.z) ? 0.0f : v.z;
        v.w = isnan(v.w) ? 0.0f : v.w;
        out[i] = v;
    }
}

__global__ void prep_pos_kernel(const float* __restrict__ seq,
                                const float* __restrict__ bos,
                                const int* __restrict__ positions,
                                float* __restrict__ out_seq,
                                float* __restrict__ out_pos)
{
    if (blockIdx.x < 4) {
        int i = blockIdx.x * 256 + threadIdx.x;
        float v = seq[i];
        out_seq[i] = isnan(v) ? bos[i & (INDIM - 1)] : v;
    } else {
        int i = threadIdx.x;
        if (i < NL * B) out_pos[i] = (float)(positions[i] + T);
    }
}

template<int KSPLIT, int GELUX>
__global__ void gemv_kernel(const float* __restrict__ X,
                            const float* __restrict__ W,
                            float* __restrict__ Y,
                            float* __restrict__ part,
                            int K, int N)
{
    __shared__ __align__(16) unsigned long long XsP[DEPTH][16][33];
    __shared__ __align__(16) float Ws[DEPTH][64][36];

    const int t    = threadIdx.x;
    const int lane = t & 31;
    const int c0   = (t >> 5) * 8;
    const int n0   = blockIdx.x * 64;
    const int Kc   = K / KSPLIT;
    const int kbase = blockIdx.y * Kc;
    const int nch  = Kc >> 5;

    const int xrow = t >> 3, xk4 = (t & 7) * 4;
    const int wrow = t >> 2, wk  = (t & 3) * 8;

    const float* xsrc  = X + (size_t)xrow * K + kbase + xk4;
    const float* xsrc2 = X + (size_t)(32 + xrow) * K + kbase + xk4;
    const float* wsrc  = W + (size_t)(n0 + wrow) * K + kbase + wk;

    const unsigned wbase = (unsigned)__cvta_generic_to_shared(&Ws[0][0][0])
                         + (unsigned)((wrow * 36 + wk) * 4);
    const unsigned WST = 64 * 36 * 4;

    #pragma unroll
    for (int p = 0; p < DEPTH - 1; p++) {
        if (p < nch) {
            cpa16(wbase + p * WST, wsrc + (size_t)p * 32);
            cpa16(wbase + p * WST + 16, wsrc + (size_t)p * 32 + 4);
        }
        CP_COMMIT();
    }
    GDW();

    float4 xr  = make_float4(0.f, 0.f, 0.f, 0.f);
    float4 xr2 = xr;
    if (0 < nch) {
        xr = *(const float4*)xsrc;
        if (GELUX) xr2 = *(const float4*)xsrc2;
    }

    unsigned long long acc[8];
    #pragma unroll
    for (int c = 0; c < 8; c++) acc[c] = 0ULL;

    int st = 0;
    int si = DEPTH - 1;
    for (int ch = 0; ch < nch; ch++) {
        CP_WAIT1();
        float4 xs = xr;
        if (GELUX) {
            xs.x = gelu1(xs.x + xr2.x);
            xs.y = gelu1(xs.y + xr2.y);
            xs.z = gelu1(xs.z + xr2.z);
            xs.w = gelu1(xs.w + xr2.w);
        }
        XsP[st][(xk4 >> 1)    ][xrow] = pk2(xs.x, xs.y);
        XsP[st][(xk4 >> 1) + 1][xrow] = pk2(xs.z, xs.w);
        __syncthreads();

        if (ch + 1 < nch) {
            xr = *(const float4*)(xsrc + (size_t)(ch + 1) * 32);
            if (GELUX) xr2 = *(const float4*)(xsrc2 + (size_t)(ch + 1) * 32);
        }

        #pragma unroll
        for (int p = 0; p < 16; p += 2) {
            unsigned long long x0 = XsP[st][p][lane];
            unsigned long long x1 = XsP[st][p + 1][lane];
            #pragma unroll
            for (int c = 0; c < 8; c++) {
                longlong2 w = *(const longlong2*)&Ws[st][c0 + c][2 * p];
                fma2(acc[c], x0, (unsigned long long)w.x);
                fma2(acc[c], x1, (unsigned long long)w.y);
            }
        }
        int nc = ch + DEPTH - 1;
        if (nc < nch) {
            cpa16(wbase + si * WST, wsrc + (size_t)nc * 32);
            cpa16(wbase + si * WST + 16, wsrc + (size_t)nc * 32 + 4);
        }
        CP_COMMIT();
        st = (st == DEPTH - 1) ? 0 : st + 1;
        si = (si == DEPTH - 1) ? 0 : si + 1;
    }

    if (KSPLIT == 1) {
        #pragma unroll
        for (int c = 0; c < 8; c++) {
            float2 p = upk(acc[c]);
            Y[(size_t)lane * N + n0 + c0 + c] = p.x + p.y;
        }
    } else {
        float* pp = part + ((size_t)blockIdx.y * 32 + lane) * N + n0 + c0;
        #pragma unroll
        for (int c = 0; c < 8; c++) {
            float2 p = upk(acc[c]);
            pp[c] = p.x + p.y;
        }
    }
}

__global__ void ln_kernel(const float* __restrict__ X,
                          const float* __restrict__ w,
                          const float* __restrict__ b,
                          float* __restrict__ Y)
{
    int tok = blockIdx.x;
    int tid = threadIdx.x;
    float wv[4], bv[4];
    #pragma unroll
    for (int j = 0; j < 4; j++) { wv[j] = w[tid + 256 * j]; bv[j] = b[tid + 256 * j]; }
    GDW();
    const float* x = X + (size_t)tok * E;
    float v[4];
    #pragma unroll
    for (int j = 0; j < 4; j++) v[j] = x[tid + 256 * j];
    float s = v[0] + v[1] + v[2] + v[3];
    #pragma unroll
    for (int o = 16; o > 0; o >>= 1) s += __shfl_xor_sync(0xffffffffu, s, o);
    __shared__ float ws[8];
    if ((tid & 31) == 0) ws[tid >> 5] = s;
    __syncthreads();
    float mean = (ws[0]+ws[1]+ws[2]+ws[3]+ws[4]+ws[5]+ws[6]+ws[7]) * (1.0f / E);
    float s2 = 0.f;
    #pragma unroll
    for (int j = 0; j < 4; j++) { float d = v[j] - mean; s2 += d * d; }
    #pragma unroll
    for (int o = 16; o > 0; o >>= 1) s2 += __shfl_xor_sync(0xffffffffu, s2, o);
    __syncthreads();
    if ((tid & 31) == 0) ws[tid >> 5] = s2;
    __syncthreads();
    float var = (ws[0]+ws[1]+ws[2]+ws[3]+ws[4]+ws[5]+ws[6]+ws[7]) * (1.0f / E);
    float r = rsqrtf(var + 1e-5f);
    #pragma unroll
    for (int j = 0; j < 4; j++) {
        int idx = tid + 256 * j;
        Y[(size_t)tok * E + idx] = (v[j] - mean) * r * wv[j] + bv[j];
    }
}

__global__ void reduce_ln_kernel(const float* __restrict__ part,
                                 float* __restrict__ x,
                                 const float* __restrict__ w,
                                 const float* __restrict__ b,
                                 float* __restrict__ xn)
{
    int tok = blockIdx.x;
    int tid = threadIdx.x;
    float wv[4], bv[4];
    #pragma unroll
    for (int j = 0; j < 4; j++) { wv[j] = w[tid + 256 * j]; bv[j] = b[tid + 256 * j]; }
    GDW();
    float v[4];
    #pragma unroll
    for (int j = 0; j < 4; j++) {
        int idx = tid + 256 * j;
        float p = 0.f;
        #pragma unroll
        for (int k = 0; k < 8; k++) p += part[((size_t)(k * 32 + tok)) * E + idx];
        float xv = x[(size_t)tok * E + idx] + p;
        x[(size_t)tok * E + idx] = xv;
        v[j] = xv;
    }
    float s = v[0] + v[1] + v[2] + v[3];
    #pragma unroll
    for (int o = 16; o > 0; o >>= 1) s += __shfl_xor_sync(0xffffffffu, s, o);
    __shared__ float ws[8];
    if ((tid & 31) == 0) ws[tid >> 5] = s;
    __syncthreads();
    float mean = (ws[0]+ws[1]+ws[2]+ws[3]+ws[4]+ws[5]+ws[6]+ws[7]) * (1.0f / E);
    float s2 = 0.f;
    #pragma unroll
    for (int j = 0; j < 4; j++) { float d = v[j] - mean; s2 += d * d; }
    #pragma unroll
    for (int o = 16; o > 0; o >>= 1) s2 += __shfl_xor_sync(0xffffffffu, s2, o);
    __syncthreads();
    if ((tid & 31) == 0) ws[tid >> 5] = s2;
    __syncthreads();
    float var = (ws[0]+ws[1]+ws[2]+ws[3]+ws[4]+ws[5]+ws[6]+ws[7]) * (1.0f / E);
    float r = rsqrtf(var + 1e-5f);
    #pragma unroll
    for (int j = 0; j < 4; j++) {
        int idx = tid + 256 * j;
        xn[(size_t)tok * E + idx] = (v[j] - mean) * r * wv[j] + bv[j];
    }
}

__global__ void reduce_ln_eos_kernel(const float* __restrict__ part,
                                     float* __restrict__ x,
                                     const float* __restrict__ w,
                                     const float* __restrict__ b,
                                     const float* __restrict__ ew,
                                     const float* __restrict__ eb,
                                     float* __restrict__ Y,
                                     float* __restrict__ out_eos)
{
    int tok = blockIdx.x;
    int tid = threadIdx.x;
    float wv[4], bv[4], ev[4];
    #pragma unroll
    for (int j = 0; j < 4; j++) {
        wv[j] = w[tid + 256 * j];
        bv[j] = b[tid + 256 * j];
        ev[j] = ew[tid + 256 * j];
    }
    GDW();
    float v[4];
    #pragma unroll
    for (int j = 0; j < 4; j++) {
        int idx = tid + 256 * j;
        float p = 0.f;
        #pragma unroll
        for (int k = 0; k < 8; k++) p += part[((size_t)(k * 32 + tok)) * E + idx];
        v[j] = x[(size_t)tok * E + idx] + p;
    }
    float s = v[0] + v[1] + v[2] + v[3];
    #pragma unroll
    for (int o = 16; o > 0; o >>= 1) s += __shfl_xor_sync(0xffffffffu, s, o);
    __shared__ float ws[8];
    if ((tid & 31) == 0) ws[tid >> 5] = s;
    __syncthreads();
    float mean = (ws[0]+ws[1]+ws[2]+ws[3]+ws[4]+ws[5]+ws[6]+ws[7]) * (1.0f / E);
    float s2 = 0.f;
    #pragma unroll
    for (int j = 0; j < 4; j++) { float d = v[j] - mean; s2 += d * d; }
    #pragma unroll
    for (int o = 16; o > 0; o >>= 1) s2 += __shfl_xor_sync(0xffffffffu, s2, o);
    __syncthreads();
    if ((tid & 31) == 0) ws[tid >> 5] = s2;
    __syncthreads();
    float var = (ws[0]+ws[1]+ws[2]+ws[3]+ws[4]+ws[5]+ws[6]+ws[7]) * (1.0f / E);
    float r = rsqrtf(var + 1e-5f);
    float ed = 0.f;
    #pragma unroll
    for (int j = 0; j < 4; j++) {
        int idx = tid + 256 * j;
        float y = (v[j] - mean) * r * wv[j] + bv[j];
        Y[(size_t)tok * E + idx] = y;
        ed += y * ev[j];
    }
    #pragma unroll
    for (int o = 16; o > 0; o >>= 1) ed += __shfl_xor_sync(0xffffffffu, ed, o);
    __syncthreads();
    if ((tid & 31) == 0) ws[tid >> 5] = ed;
    __syncthreads();
    if (tid == 0)
        out_eos[tok] = ws[0]+ws[1]+ws[2]+ws[3]+ws[4]+ws[5]+ws[6]+ws[7] + eb[0];
}

#define SMAX 1056
__global__ void attn_rope_kernel(const float* __restrict__ part,
                                 const int* __restrict__ pos_l,
                                 float* __restrict__ kcache,
                                 float* __restrict__ vcache,
                                 float* __restrict__ out)
{
    __shared__ float qs[4][64];
    __shared__ __align__(16) float kn[4][64];
    __shared__ __align__(16) float vn[4][64];
    __shared__ float sc[4][SMAX];
    __shared__ float red[8];
    __shared__ float inv[4];
    __shared__ float vpart[4][4][64];

    int bh = blockIdx.x;
    int b = bh >> 4, h = bh & 15;
    int tid = threadIdx.x;
    int pos = pos_l[b];
    GDW();
    int slen = pos + T;
    const float LOGC = logf(10000.0f) / 32.0f;

    if (tid < 128) {
        int t = tid >> 5, j = tid & 31;
        int tok = b * T + t;
        size_t base = (size_t)tok * 3072 + h * 64 + 2 * j;
        float p0 = part[base]                 + part[base + 32 * 3072]
                 + part[base + 64 * 3072]     + part[base + 96 * 3072];
        float p1 = part[base + 1]             + part[base + 1 + 32 * 3072]
                 + part[base + 1 + 64 * 3072] + part[base + 1 + 96 * 3072];
        float freq = __expf(-(float)j * LOGC);
        float sn, cs;
        sincosf((float)(pos + t) * freq, &sn, &cs);
        qs[t][2 * j]     = p0 * cs - p1 * sn;
        qs[t][2 * j + 1] = p0 * sn + p1 * cs;
    } else {
        int t = (tid - 128) >> 5, j = (tid - 128) & 31;
        int tok = b * T + t;
        size_t base = (size_t)tok * 3072 + E + h * 64 + 2 * j;
        float p0 = part[base]                 + part[base + 32 * 3072]
                 + part[base + 64 * 3072]     + part[base + 96 * 3072];
        float p1 = part[base + 1]             + part[base + 1 + 32 * 3072]
                 + part[base + 1 + 64 * 3072] + part[base + 1 + 96 * 3072];
        float freq = __expf(-(float)j * LOGC);
        float sn, cs;
        sincosf((float)(pos + t) * freq, &sn, &cs);
        float k0 = p0 * cs - p1 * sn;
        float k1 = p0 * sn + p1 * cs;
        kn[t][2 * j]     = k0;
        kn[t][2 * j + 1] = k1;
        int slot = (pos + t) % L;
        size_t off = ((size_t)b * L + slot) * E + h * D + 2 * j;
        kcache[off]     = k0;
        kcache[off + 1] = k1;
    }
    {
        int t = tid >> 6, d = tid & 63;
        int tok = b * T + t;
        size_t base = (size_t)tok * 3072 + 2 * E + h * 64 + d;
        float p = part[base]                 + part[base + 32 * 3072]
                + part[base + 64 * 3072]     + part[base + 96 * 3072];
        vn[t][d] = p;
        int slot = (pos + t) % L;
        vcache[((size_t)b * L + slot) * E + h * D + d] = p;
    }
    __syncthreads();

    const float scale = 0.125f;
    for (int s = tid; s < slen; s += 256) {
        bool old = (s < pos);
        const float4* kr = old
            ? (const float4*)(kcache + ((size_t)b * L + s) * E + h * D)
            : (const float4*)&kn[s - pos][0];
        float d0 = 0.f, d1 = 0.f, d2 = 0.f, d3 = 0.f;
        #pragma unroll
        for (int i4 = 0; i4 < 16; i4++) {
            float4 kv = kr[i4];
            int d = i4 * 4;
            d0 += qs[0][d]*kv.x + qs[0][d+1]*kv.y + qs[0][d+2]*kv.z + qs[0][d+3]*kv.w;
            d1 += qs[1][d]*kv.x + qs[1][d+1]*kv.y + qs[1][d+2]*kv.z + qs[1][d+3]*kv.w;
            d2 += qs[2][d]*kv.x + qs[2][d+1]*kv.y + qs[2][d+2]*kv.z + qs[2][d+3]*kv.w;
            d3 += qs[3][d]*kv.x + qs[3][d+1]*kv.y + qs[3][d+2]*kv.z + qs[3][d+3]*kv.w;
        }
        sc[0][s] = (s <= pos + 0) ? d0 * scale : -1e30f;
        sc[1][s] = (s <= pos + 1) ? d1 * scale : -1e30f;
        sc[2][s] = (s <= pos + 2) ? d2 * scale : -1e30f;
        sc[3][s] = (s <= pos + 3) ? d3 * scale : -1e30f;
    }
    __syncthreads();

    #pragma unroll
    for (int t = 0; t < 4; t++) {
        float m = -1e30f;
        for (int s = tid; s < slen; s += 256) m = fmaxf(m, sc[t][s]);
        #pragma unroll
        for (int o = 16; o > 0; o >>= 1) m = fmaxf(m, __shfl_xor_sync(0xffffffffu, m, o));
        if ((tid & 31) == 0) red[tid >> 5] = m;
        __syncthreads();
        m = fmaxf(fmaxf(fmaxf(red[0], red[1]), fmaxf(red[2], red[3])),
                  fmaxf(fmaxf(red[4], red[5]), fmaxf(red[6], red[7])));
        float ssum = 0.f;
        for (int s = tid; s < slen; s += 256) {
            float e = __expf(sc[t][s] - m);
            sc[t][s] = e;
            ssum += e;
        }
        #pragma unroll
        for (int o = 16; o > 0; o >>= 1) ssum += __shfl_xor_sync(0xffffffffu, ssum, o);
        __syncthreads();
        if ((tid & 31) == 0) red[tid >> 5] = ssum;
        __syncthreads();
        if (tid == 0)
            inv[t] = 1.0f / (red[0]+red[1]+red[2]+red[3]+red[4]+red[5]+red[6]+red[7]);
        __syncthreads();
    }

    {
        int sg = tid >> 6, d = tid & 63;
        int chunk = (slen + 3) >> 2;
        int s0 = sg * chunk;
        int s1 = min(slen, s0 + chunk);
        float a0 = 0.f, a1 = 0.f, a2 = 0.f, a3 = 0.f;
        for (int s = s0; s < s1; s++) {
            bool old = (s < pos);
            float v0 = old ? vcache[((size_t)b * L + s) * E + h * D + d]
                           : vn[s - pos][d];
            a0 += sc[0][s] * v0;
            a1 += sc[1][s] * v0;
            a2 += sc[2][s] * v0;
            a3 += sc[3][s] * v0;
        }
        vpart[sg][0][d] = a0;
        vpart[sg][1][d] = a1;
        vpart[sg][2][d] = a2;
        vpart[sg][3][d] = a3;
    }
    __syncthreads();
    {
        int t = tid >> 6, d = tid & 63;
        float sum = vpart[0][t][d] + vpart[1][t][d] + vpart[2][t][d] + vpart[3][t][d];
        out[((size_t)(b * T + t) * E) + h * D + d] = sum * inv[t];
    }
}

template<typename F, typename... Args>
static inline void pdl(dim3 g, dim3 blk, F f, Args... args)
{
    cudaLaunchAttribute at[1];
    at[0].id = cudaLaunchAttributeProgrammaticStreamSerialization;
    at[0].val.programmaticStreamSerializationAllowed = 1;
    cudaLaunchConfig_t cfg = {};
    cfg.gridDim = g;
    cfg.blockDim = blk;
    cfg.dynamicSmemBytes = 0;
    cfg.stream = 0;
    cfg.attrs = at;
    cfg.numAttrs = 1;
    cudaLaunchKernelEx(&cfg, f, args...);
}

extern "C" void kernel_launch(void* const* d_in, const int* in_sizes, int n_in,
                              void* d_out, int out_size)
{
    const float* seq       = (const float*)d_in[0];
    const float* bos       = (const float*)d_in[1];
    const float* caches    = (const float*)d_in[2];
    const int*   positions = (const int*)  d_in[3];
    const float* in_w      = (const float*)d_in[4];
    const float* ip_w      = (const float*)d_in[5];
    const float* op_w      = (const float*)d_in[6];
    const float* n1w       = (const float*)d_in[7];
    const float* n1b       = (const float*)d_in[8];
    const float* n2w       = (const float*)d_in[9];
    const float* n2b       = (const float*)d_in[10];
    const float* l1_w      = (const float*)d_in[11];
    const float* l2_w      = (const float*)d_in[12];
    const float* on_w      = (const float*)d_in[13];
    const float* on_b      = (const float*)d_in[14];
    const float* eos_w     = (const float*)d_in[15];
    const float* eos_b     = (const float*)d_in[16];

    float* out = (float*)d_out;
    const size_t cache_elems = (size_t)NL * 2 * B * L * E;
    float* out_x     = out;
    float* out_eos   = out + (size_t)NTOK * E;
    float* out_cache = out_eos + NTOK;
    float* out_pos   = out_cache + cache_elems;

    float *px, *pxn, *pattn, *pseq, *ppart;
    cudaGetSymbolAddress((void**)&px,    g_x);
    cudaGetSymbolAddress((void**)&pxn,   g_xn);
    cudaGetSymbolAddress((void**)&pattn, g_attn);
    cudaGetSymbolAddress((void**)&pseq,  g_seq);
    cudaGetSymbolAddress((void**)&ppart, g_part);
    float* ppart2 = ppart + 262144;   // disjoint region for op/l2 partials

    long nf4 = (long)(cache_elems / 4);
    cache_copy_kernel<<<(unsigned)((nf4 + 255) / 256), 256>>>((const float4*)caches,
                                                              (float4*)out_cache, nf4);

    pdl(dim3(5), dim3(256), prep_pos_kernel, seq, bos, positions, pseq, out_pos);
    pdl(dim3(E / 64, 1), dim3(256), gemv_kernel<1, 0>,
        (const float*)pseq, in_w, px, (float*)nullptr, (int)INDIM, (int)E);
    pdl(dim3(NTOK), dim3(256), ln_kernel, (const float*)px, n1w, n1b, pxn);

    for (int i = 0; i < NL; i++) {
        const float* ipw = ip_w + (size_t)i * 3 * E * E;
        const float* opw = op_w + (size_t)i * E * E;
        const float* l1  = l1_w + (size_t)i * FF * E;
        const float* l2  = l2_w + (size_t)i * E * FF;
        float* kcache = out_cache + ((size_t)i * 2 + 0) * B * L * E;
        float* vcache = out_cache + ((size_t)i * 2 + 1) * B * L * E;
        const int* posl = positions + i * B;

        // qkv: K=1024, N=3072, split-K=4 -> 192 blocks; partials in region A
        pdl(dim3(3 * E / 64, 4), dim3(256), gemv_kernel<4, 0>,
            (const float*)ppart == nullptr ? nullptr : (const float*)pxn, ipw,
            (float*)nullptr, ppart, (int)E, (int)(3 * E));

        // attention fused with qkv-reduce + rope + cache scatter
        pdl(dim3(B * H), dim3(256), attn_rope_kernel,
            (const float*)ppart, posl, kcache, vcache, pattn);

        // op: K=1024, N=1024, split-K=8 -> region B; fused reduce+add+LN
        pdl(dim3(E / 64, 8), dim3(256), gemv_kernel<8, 0>,
            (const float*)pattn, opw, (float*)nullptr, ppart2, (int)E, (int)E);
        pdl(dim3(NTOK), dim3(256), reduce_ln_kernel,
            (const float*)ppart2, px, n2w + (size_t)i * E, n2b + (size_t)i * E, pxn);

        // l1: K=1024, N=4096, split-K=2 -> region A (raw partials)
        pdl(dim3(FF / 64, 2), dim3(256), gemv_kernel<2, 0>,
            (const float*)pxn, l1, (float*)nullptr, ppart, (int)E, (int)FF);

        // l2: K=4096, N=1024, split-K=8; gelu fused in X loader; out -> region B
        pdl(dim3(E / 64, 8), dim3(256), gemv_kernel<8, 1>,
            (const float*)ppart, l2, (float*)nullptr, ppart2, (int)FF, (int)E);

        if (i + 1 < NL) {
            pdl(dim3(NTOK), dim3(256), reduce_ln_kernel,
                (const float*)ppart2, px,
                n1w + (size_t)(i + 1) * E, n1b + (size_t)(i + 1) * E, pxn);
        } else {
            pdl(dim3(NTOK), dim3(256), reduce_ln_eos_kernel,
                (const float*)ppart2, px, on_w, on_b, eos_w, eos_b,
                out_x, out_eos);
        }
    }
}

// round 17
// speedup vs baseline: 1.1122x; 1.1122x over previous
#include <cuda_runtime.h>
#include <math.h>

#define NL 6
#define B  8
#define T  4
#define L  2048
#define H  16
#define D  64
#define E  1024
#define FF 4096
#define INDIM 32
#define NTOK 32
#define DEPTH 4

#define CACHE_F4 50331648LL

#define GDW() asm volatile("griddepcontrol.wait;" ::: "memory")

__device__ __align__(16) float g_x   [NTOK * E];
__device__ __align__(16) float g_xn  [NTOK * E];
__device__ __align__(16) float g_q   [NTOK * E];
__device__ __align__(16) float g_attn[NTOK * E];
__device__ __align__(16) float g_h   [NTOK * FF];
__device__ __align__(16) float g_seq [NTOK * INDIM];
__device__ __align__(16) float g_part[524288];

__device__ __forceinline__ unsigned long long pk2(float lo, float hi) {
    unsigned long long r;
    asm("mov.b64 %0, {%1, %2};" : "=l"(r) : "f"(lo), "f"(hi));
    return r;
}
__device__ __forceinline__ void fma2(unsigned long long& d,
                                     unsigned long long a,
                                     unsigned long long b) {
    asm("fma.rn.f32x2 %0, %1, %2, %3;" : "=l"(d) : "l"(a), "l"(b), "l"(d));
}
__device__ __forceinline__ float2 upk(unsigned long long v) {
    float2 f;
    asm("mov.b64 {%0, %1}, %2;" : "=f"(f.x), "=f"(f.y) : "l"(v));
    return f;
}
__device__ __forceinline__ void cpa16(unsigned dst, const void* src) {
    asm volatile("cp.async.ca.shared.global [%0], [%1], 16;" :: "r"(dst), "l"(src));
}
#define CP_COMMIT() asm volatile("cp.async.commit_group;")
#define CP_WAIT2()  asm volatile("cp.async.wait_group 2;")

__global__ void cache_copy_kernel(const float4* __restrict__ in,
                                  float4* __restrict__ out, long n)
{
    long i = (long)blockIdx.x * blockDim.x + threadIdx.x;
    if (i < n) {
        float4 v = in[i];
        v.x = isnan(v.x) ? 0.0f : v.x;
        v.y = isnan(v.y) ? 0.0f : v.y;
        v.z = isnan(v.z) ? 0.0f : v.z;
        v.w = isnan(v.w) ? 0.0f : v.w;
        out[i] = v;
    }
}

__global__ void prep_pos_kernel(const float* __restrict__ seq,
                                const float* __restrict__ bos,
                                const int* __restrict__ positions,
                                float* __restrict__ out_seq,
                                float* __restrict__ out_pos)
{
    if (blockIdx.x < 4) {
        int i = blockIdx.x * 256 + threadIdx.x;
        float v = seq[i];
        out_seq[i] = isnan(v) ? bos[i & (INDIM - 1)] : v;
    } else {
        int i = threadIdx.x;
        if (i < NL * B) out_pos[i] = (float)(positions[i] + T);
    }
}

// ======== GEMM: Y[32,N] = X[32,K] @ W[N,K]^T ========
// W: cp.async 4-stage pipeline (3 in flight), prefetched BEFORE the PDL wait.
// X: float4 post-wait, 1-ahead prefetch, transposed-packed smem; 1 barrier/chunk.
template<int KSPLIT>
__global__ void gemv_kernel(const float* __restrict__ X,
                            const float* __restrict__ W,
                            float* __restrict__ Y,
                            float* __restrict__ part,
                            int K, int N)
{
    __shared__ __align__(16) unsigned long long XsP[DEPTH][16][33];
    __shared__ __align__(16) float Ws[DEPTH][64][36];

    const int t    = threadIdx.x;
    const int lane = t & 31;
    const int c0   = (t >> 5) * 8;
    const int n0   = blockIdx.x * 64;
    const int Kc   = K / KSPLIT;
    const int kbase = blockIdx.y * Kc;
    const int nch  = Kc >> 5;

    const int xrow = t >> 3, xk4 = (t & 7) * 4;
    const int wrow = t >> 2, wk  = (t & 3) * 8;

    const float* xsrc = X + (size_t)xrow * K + kbase + xk4;
    const float* wsrc = W + (size_t)(n0 + wrow) * K + kbase + wk;

    const unsigned wbase = (unsigned)__cvta_generic_to_shared(&Ws[0][0][0])
                         + (unsigned)((wrow * 36 + wk) * 4);
    const unsigned WST = 64 * 36 * 4;

    // W prefetch stages 0..DEPTH-2 (3 stages, launch-independent, pre-wait)
    #pragma unroll
    for (int p = 0; p < DEPTH - 1; p++) {
        if (p < nch) {
            cpa16(wbase + p * WST, wsrc + (size_t)p * 32);
            cpa16(wbase + p * WST + 16, wsrc + (size_t)p * 32 + 4);
        }
        CP_COMMIT();
    }
    GDW();   // predecessor output (X) now valid

    float4 xr = make_float4(0.f, 0.f, 0.f, 0.f);
    if (0 < nch) xr = *(const float4*)xsrc;

    unsigned long long acc[8];
    #pragma unroll
    for (int c = 0; c < 8; c++) acc[c] = 0ULL;

    int st = 0;
    int si = DEPTH - 1;
    for (int ch = 0; ch < nch; ch++) {
        CP_WAIT2();
        XsP[st][(xk4 >> 1)    ][xrow] = pk2(xr.x, xr.y);
        XsP[st][(xk4 >> 1) + 1][xrow] = pk2(xr.z, xr.w);
        __syncthreads();

        if (ch + 1 < nch) xr = *(const float4*)(xsrc + (size_t)(ch + 1) * 32);

        #pragma unroll
        for (int p = 0; p < 16; p += 2) {
            unsigned long long x0 = XsP[st][p][lane];
            unsigned long long x1 = XsP[st][p + 1][lane];
            #pragma unroll
            for (int c = 0; c < 8; c++) {
                longlong2 w = *(const longlong2*)&Ws[st][c0 + c][2 * p];
                fma2(acc[c], x0, (unsigned long long)w.x);
                fma2(acc[c], x1, (unsigned long long)w.y);
            }
        }
        int nc = ch + DEPTH - 1;
        if (nc < nch) {
            cpa16(wbase + si * WST, wsrc + (size_t)nc * 32);
            cpa16(wbase + si * WST + 16, wsrc + (size_t)nc * 32 + 4);
        }
        CP_COMMIT();
        st = (st == DEPTH - 1) ? 0 : st + 1;
        si = (si == DEPTH - 1) ? 0 : si + 1;
    }

    if (KSPLIT == 1) {
        #pragma unroll
        for (int c = 0; c < 8; c++) {
            float2 p = upk(acc[c]);
            Y[(size_t)lane * N + n0 + c0 + c] = p.x + p.y;
        }
    } else {
        float* pp = part + ((size_t)blockIdx.y * 32 + lane) * N + n0 + c0;
        #pragma unroll
        for (int c = 0; c < 8; c++) {
            float2 p = upk(acc[c]);
            pp[c] = p.x + p.y;
        }
    }
}

template<int KS>
__global__ void reduce_gelu_kernel(const float* __restrict__ part,
                                   float* __restrict__ Y, int N)
{
    GDW();
    int i = blockIdx.x * 256 + threadIdx.x;
    if (i >= 32 * N) return;
    int r = i / N, n = i - r * N;
    float s = 0.f;
    #pragma unroll
    for (int k = 0; k < KS; k++) s += part[((size_t)k * 32 + r) * N + n];
    Y[i] = 0.5f * s * (1.0f + erff(s * 0.70710678118654752f));
}

__global__ void reduce_rope_kernel(const float* __restrict__ part,
                                   const int* __restrict__ pos_l,
                                   float* __restrict__ qout,
                                   float* __restrict__ kcache,
                                   float* __restrict__ vcache)
{
    int id = blockIdx.x * 256 + threadIdx.x;
    int tok = id / 1536;
    int f   = (id - tok * 1536) * 2;
    int b = tok >> 2, t = tok & 3;
    int pos = pos_l[b];
    GDW();
    float s0 = 0.f, s1 = 0.f;
    #pragma unroll
    for (int k = 0; k < 4; k++) {
        const float* p = part + ((size_t)(k * 32 + tok) * 3072) + f;
        s0 += p[0];
        s1 += p[1];
    }
    if (f < E) {
        int j = (f & 63) >> 1;
        float freq = __expf(-(float)j * (logf(10000.0f) / 32.0f));
        float sn, cs;
        sincosf((float)(pos + t) * freq, &sn, &cs);
        qout[(size_t)tok * E + f]     = s0 * cs - s1 * sn;
        qout[(size_t)tok * E + f + 1] = s0 * sn + s1 * cs;
    } else if (f < 2 * E) {
        int fk = f - E;
        int j = (fk & 63) >> 1;
        float freq = __expf(-(float)j * (logf(10000.0f) / 32.0f));
        float sn, cs;
        sincosf((float)(pos + t) * freq, &sn, &cs);
        int slot = (pos + t) % L;
        size_t off = ((size_t)b * L + slot) * E + fk;
        kcache[off]     = s0 * cs - s1 * sn;
        kcache[off + 1] = s0 * sn + s1 * cs;
    } else {
        int fv = f - 2 * E;
        int slot = (pos + t) % L;
        size_t off = ((size_t)b * L + slot) * E + fv;
        vcache[off]     = s0;
        vcache[off + 1] = s1;
    }
}

__global__ void ln_kernel(const float* __restrict__ X,
                          const float* __restrict__ w,
                          const float* __restrict__ b,
                          float* __restrict__ Y)
{
    int tok = blockIdx.x;
    int tid = threadIdx.x;
    float wv[4], bv[4];
    #pragma unroll
    for (int j = 0; j < 4; j++) { wv[j] = w[tid + 256 * j]; bv[j] = b[tid + 256 * j]; }
    GDW();
    const float* x = X + (size_t)tok * E;
    float v[4];
    #pragma unroll
    for (int j = 0; j < 4; j++) v[j] = x[tid + 256 * j];
    float s = v[0] + v[1] + v[2] + v[3];
    #pragma unroll
    for (int o = 16; o > 0; o >>= 1) s += __shfl_xor_sync(0xffffffffu, s, o);
    __shared__ float ws[8];
    if ((tid & 31) == 0) ws[tid >> 5] = s;
    __syncthreads();
    float mean = (ws[0]+ws[1]+ws[2]+ws[3]+ws[4]+ws[5]+ws[6]+ws[7]) * (1.0f / E);
    float s2 = 0.f;
    #pragma unroll
    for (int j = 0; j < 4; j++) { float d = v[j] - mean; s2 += d * d; }
    #pragma unroll
    for (int o = 16; o > 0; o >>= 1) s2 += __shfl_xor_sync(0xffffffffu, s2, o);
    __syncthreads();
    if ((tid & 31) == 0) ws[tid >> 5] = s2;
    __syncthreads();
    float var = (ws[0]+ws[1]+ws[2]+ws[3]+ws[4]+ws[5]+ws[6]+ws[7]) * (1.0f / E);
    float r = rsqrtf(var + 1e-5f);
    #pragma unroll
    for (int j = 0; j < 4; j++) {
        int idx = tid + 256 * j;
        Y[(size_t)tok * E + idx] = (v[j] - mean) * r * wv[j] + bv[j];
    }
}

__global__ void reduce_ln_kernel(const float* __restrict__ part,
                                 float* __restrict__ x,
                                 const float* __restrict__ w,
                                 const float* __restrict__ b,
                                 float* __restrict__ xn)
{
    int tok = blockIdx.x;
    int tid = threadIdx.x;
    float wv[4], bv[4];
    #pragma unroll
    for (int j = 0; j < 4; j++) { wv[j] = w[tid + 256 * j]; bv[j] = b[tid + 256 * j]; }
    GDW();
    float v[4];
    #pragma unroll
    for (int j = 0; j < 4; j++) {
        int idx = tid + 256 * j;
        float p = 0.f;
        #pragma unroll
        for (int k = 0; k < 8; k++) p += part[((size_t)(k * 32 + tok)) * E + idx];
        float xv = x[(size_t)tok * E + idx] + p;
        x[(size_t)tok * E + idx] = xv;
        v[j] = xv;
    }
    float s = v[0] + v[1] + v[2] + v[3];
    #pragma unroll
    for (int o = 16; o > 0; o >>= 1) s += __shfl_xor_sync(0xffffffffu, s, o);
    __shared__ float ws[8];
    if ((tid & 31) == 0) ws[tid >> 5] = s;
    __syncthreads();
    float mean = (ws[0]+ws[1]+ws[2]+ws[3]+ws[4]+ws[5]+ws[6]+ws[7]) * (1.0f / E);
    float s2 = 0.f;
    #pragma unroll
    for (int j = 0; j < 4; j++) { float d = v[j] - mean; s2 += d * d; }
    #pragma unroll
    for (int o = 16; o > 0; o >>= 1) s2 += __shfl_xor_sync(0xffffffffu, s2, o);
    __syncthreads();
    if ((tid & 31) == 0) ws[tid >> 5] = s2;
    __syncthreads();
    float var = (ws[0]+ws[1]+ws[2]+ws[3]+ws[4]+ws[5]+ws[6]+ws[7]) * (1.0f / E);
    float r = rsqrtf(var + 1e-5f);
    #pragma unroll
    for (int j = 0; j < 4; j++) {
        int idx = tid + 256 * j;
        xn[(size_t)tok * E + idx] = (v[j] - mean) * r * wv[j] + bv[j];
    }
}

__global__ void reduce_ln_eos_kernel(const float* __restrict__ part,
                                     float* __restrict__ x,
                                     const float* __restrict__ w,
                                     const float* __restrict__ b,
                                     const float* __restrict__ ew,
                                     const float* __restrict__ eb,
                                     float* __restrict__ Y,
                                     float* __restrict__ out_eos)
{
    int tok = blockIdx.x;
    int tid = threadIdx.x;
    float wv[4], bv[4], ev[4];
    #pragma unroll
    for (int j = 0; j < 4; j++) {
        wv[j] = w[tid + 256 * j];
        bv[j] = b[tid + 256 * j];
        ev[j] = ew[tid + 256 * j];
    }
    GDW();
    float v[4];
    #pragma unroll
    for (int j = 0; j < 4; j++) {
        int idx = tid + 256 * j;
        float p = 0.f;
        #pragma unroll
        for (int k = 0; k < 8; k++) p += part[((size_t)(k * 32 + tok)) * E + idx];
        v[j] = x[(size_t)tok * E + idx] + p;
    }
    float s = v[0] + v[1] + v[2] + v[3];
    #pragma unroll
    for (int o = 16; o > 0; o >>= 1) s += __shfl_xor_sync(0xffffffffu, s, o);
    __shared__ float ws[8];
    if ((tid & 31) == 0) ws[tid >> 5] = s;
    __syncthreads();
    float mean = (ws[0]+ws[1]+ws[2]+ws[3]+ws[4]+ws[5]+ws[6]+ws[7]) * (1.0f / E);
    float s2 = 0.f;
    #pragma unroll
    for (int j = 0; j < 4; j++) { float d = v[j] - mean; s2 += d * d; }
    #pragma unroll
    for (int o = 16; o > 0; o >>= 1) s2 += __shfl_xor_sync(0xffffffffu, s2, o);
    __syncthreads();
    if ((tid & 31) == 0) ws[tid >> 5] = s2;
    __syncthreads();
    float var = (ws[0]+ws[1]+ws[2]+ws[3]+ws[4]+ws[5]+ws[6]+ws[7]) * (1.0f / E);
    float r = rsqrtf(var + 1e-5f);
    float ed = 0.f;
    #pragma unroll
    for (int j = 0; j < 4; j++) {
        int idx = tid + 256 * j;
        float y = (v[j] - mean) * r * wv[j] + bv[j];
        Y[(size_t)tok * E + idx] = y;
        ed += y * ev[j];
    }
    #pragma unroll
    for (int o = 16; o > 0; o >>= 1) ed += __shfl_xor_sync(0xffffffffu, ed, o);
    __syncthreads();
    if ((tid & 31) == 0) ws[tid >> 5] = ed;
    __syncthreads();
    if (tid == 0)
        out_eos[tok] = ws[0]+ws[1]+ws[2]+ws[3]+ws[4]+ws[5]+ws[6]+ws[7] + eb[0];
}

#define SMAX 1056
__global__ void attn_kernel(const float* __restrict__ q,
                            const float* __restrict__ kc,
                            const float* __restrict__ vc,
                            const int* __restrict__ pos_l,
                            float* __restrict__ out)
{
    __shared__ float qs[4][64];
    __shared__ float sc[4][SMAX];
    __shared__ float red[8];
    __shared__ float inv[4];
    __shared__ float vpart[4][4][64];

    int bh = blockIdx.x;
    int b = bh >> 4, h = bh & 15;
    int tid = threadIdx.x;
    int pos = pos_l[b];
    GDW();
    int slen = pos + T;

    {
        int t = tid >> 6, d = tid & 63;
        qs[t][d] = q[((size_t)(b * T + t) * E) + h * D + d];
    }
    __syncthreads();

    const float scale = 0.125f;
    for (int s = tid; s < slen; s += 256) {
        const float4* kr = (const float4*)(kc + ((size_t)b * L + s) * E + h * D);
        float d0 = 0.f, d1 = 0.f, d2 = 0.f, d3 = 0.f;
        #pragma unroll
        for (int i4 = 0; i4 < 16; i4++) {
            float4 kv = kr[i4];
            int d = i4 * 4;
            d0 += qs[0][d]*kv.x + qs[0][d+1]*kv.y + qs[0][d+2]*kv.z + qs[0][d+3]*kv.w;
            d1 += qs[1][d]*kv.x + qs[1][d+1]*kv.y + qs[1][d+2]*kv.z + qs[1][d+3]*kv.w;
            d2 += qs[2][d]*kv.x + qs[2][d+1]*kv.y + qs[2][d+2]*kv.z + qs[2][d+3]*kv.w;
            d3 += qs[3][d]*kv.x + qs[3][d+1]*kv.y + qs[3][d+2]*kv.z + qs[3][d+3]*kv.w;
        }
        sc[0][s] = (s <= pos + 0) ? d0 * scale : -1e30f;
        sc[1][s] = (s <= pos + 1) ? d1 * scale : -1e30f;
        sc[2][s] = (s <= pos + 2) ? d2 * scale : -1e30f;
        sc[3][s] = (s <= pos + 3) ? d3 * scale : -1e30f;
    }
    __syncthreads();

    #pragma unroll
    for (int t = 0; t < 4; t++) {
        float m = -1e30f;
        for (int s = tid; s < slen; s += 256) m = fmaxf(m, sc[t][s]);
        #pragma unroll
        for (int o = 16; o > 0; o >>= 1) m = fmaxf(m, __shfl_xor_sync(0xffffffffu, m, o));
        if ((tid & 31) == 0) red[tid >> 5] = m;
        __syncthreads();
        m = fmaxf(fmaxf(fmaxf(red[0], red[1]), fmaxf(red[2], red[3])),
                  fmaxf(fmaxf(red[4], red[5]), fmaxf(red[6], red[7])));
        float ssum = 0.f;
        for (int s = tid; s < slen; s += 256) {
            float e = __expf(sc[t][s] - m);
            sc[t][s] = e;
            ssum += e;
        }
        #pragma unroll
        for (int o = 16; o > 0; o >>= 1) ssum += __shfl_xor_sync(0xffffffffu, ssum, o);
        __syncthreads();
        if ((tid & 31) == 0) red[tid >> 5] = ssum;
        __syncthreads();
        if (tid == 0)
            inv[t] = 1.0f / (red[0]+red[1]+red[2]+red[3]+red[4]+red[5]+red[6]+red[7]);
        __syncthreads();
    }

    {
        int sg = tid >> 6, d = tid & 63;
        int chunk = (slen + 3) >> 2;
        int s0 = sg * chunk;
        int s1 = min(slen, s0 + chunk);
        const float* vp = vc + (size_t)b * L * E + h * D + d;
        float a0 = 0.f, a1 = 0.f, a2 = 0.f, a3 = 0.f;
        int s = s0;
        for (; s + 2 <= s1; s += 2) {
            float v0 = vp[(size_t)s * E];
            float v1 = vp[(size_t)(s + 1) * E];
            a0 += sc[0][s] * v0 + sc[0][s+1] * v1;
            a1 += sc[1][s] * v0 + sc[1][s+1] * v1;
            a2 += sc[2][s] * v0 + sc[2][s+1] * v1;
            a3 += sc[3][s] * v0 + sc[3][s+1] * v1;
        }
        if (s < s1) {
            float v0 = vp[(size_t)s * E];
            a0 += sc[0][s] * v0;
            a1 += sc[1][s] * v0;
            a2 += sc[2][s] * v0;
            a3 += sc[3][s] * v0;
        }
        vpart[sg][0][d] = a0;
        vpart[sg][1][d] = a1;
        vpart[sg][2][d] = a2;
        vpart[sg][3][d] = a3;
    }
    __syncthreads();
    {
        int t = tid >> 6, d = tid & 63;
        float sum = vpart[0][t][d] + vpart[1][t][d] + vpart[2][t][d] + vpart[3][t][d];
        out[((size_t)(b * T + t) * E) + h * D + d] = sum * inv[t];
    }
}

template<typename F, typename... Args>
static inline void pdl(dim3 g, dim3 blk, F f, Args... args)
{
    cudaLaunchAttribute at[1];
    at[0].id = cudaLaunchAttributeProgrammaticStreamSerialization;
    at[0].val.programmaticStreamSerializationAllowed = 1;
    cudaLaunchConfig_t cfg = {};
    cfg.gridDim = g;
    cfg.blockDim = blk;
    cfg.dynamicSmemBytes = 0;
    cfg.stream = 0;
    cfg.attrs = at;
    cfg.numAttrs = 1;
    cudaLaunchKernelEx(&cfg, f, args...);
}

extern "C" void kernel_launch(void* const* d_in, const int* in_sizes, int n_in,
                              void* d_out, int out_size)
{
    const float* seq       = (const float*)d_in[0];
    const float* bos       = (const float*)d_in[1];
    const float* caches    = (const float*)d_in[2];
    const int*   positions = (const int*)  d_in[3];
    const float* in_w      = (const float*)d_in[4];
    const float* ip_w      = (const float*)d_in[5];
    const float* op_w      = (const float*)d_in[6];
    const float* n1w       = (const float*)d_in[7];
    const float* n1b       = (const float*)d_in[8];
    const float* n2w       = (const float*)d_in[9];
    const float* n2b       = (const float*)d_in[10];
    const float* l1_w      = (const float*)d_in[11];
    const float* l2_w      = (const float*)d_in[12];
    const float* on_w      = (const float*)d_in[13];
    const float* on_b      = (const float*)d_in[14];
    const float* eos_w     = (const float*)d_in[15];
    const float* eos_b     = (const float*)d_in[16];

    float* out = (float*)d_out;
    const size_t cache_elems = (size_t)NL * 2 * B * L * E;
    float* out_x     = out;
    float* out_eos   = out + (size_t)NTOK * E;
    float* out_cache = out_eos + NTOK;
    float* out_pos   = out_cache + cache_elems;

    float *px, *pxn, *pq, *pattn, *ph, *pseq, *ppart;
    cudaGetSymbolAddress((void**)&px,    g_x);
    cudaGetSymbolAddress((void**)&pxn,   g_xn);
    cudaGetSymbolAddress((void**)&pq,    g_q);
    cudaGetSymbolAddress((void**)&pattn, g_attn);
    cudaGetSymbolAddress((void**)&ph,    g_h);
    cudaGetSymbolAddress((void**)&pseq,  g_seq);
    cudaGetSymbolAddress((void**)&ppart, g_part);

    long nf4 = (long)(cache_elems / 4);
    cache_copy_kernel<<<(unsigned)((nf4 + 255) / 256), 256>>>((const float4*)caches,
                                                              (float4*)out_cache, nf4);

    pdl(dim3(5), dim3(256), prep_pos_kernel, seq, bos, positions, pseq, out_pos);
    pdl(dim3(E / 64, 1), dim3(256), gemv_kernel<1>,
        (const float*)pseq, in_w, px, (float*)nullptr, (int)INDIM, (int)E);
    pdl(dim3(NTOK), dim3(256), ln_kernel, (const float*)px, n1w, n1b, pxn);

    for (int i = 0; i < NL; i++) {
        const float* ipw = ip_w + (size_t)i * 3 * E * E;
        const float* opw = op_w + (size_t)i * E * E;
        const float* l1  = l1_w + (size_t)i * FF * E;
        const float* l2  = l2_w + (size_t)i * E * FF;
        float* kcache = out_cache + ((size_t)i * 2 + 0) * B * L * E;
        float* vcache = out_cache + ((size_t)i * 2 + 1) * B * L * E;
        const int* posl = positions + i * B;

        // qkv: K=1024, N=3072, split-K=4 -> 192 blocks
        pdl(dim3(3 * E / 64, 4), dim3(256), gemv_kernel<4>,
            (const float*)pxn, ipw, (float*)nullptr, ppart, (int)E, (int)(3 * E));
        pdl(dim3(192), dim3(256), reduce_rope_kernel,
            (const float*)ppart, posl, pq, kcache, vcache);

        // attention: single kernel, one block per (b,h)
        pdl(dim3(B * H), dim3(256), attn_kernel,
            (const float*)pq, (const float*)kcache, (const float*)vcache, posl,
            pattn);

        // op: K=1024, N=1024, split-K=8 -> 128 blocks; fused reduce+add+LN
        pdl(dim3(E / 64, 8), dim3(256), gemv_kernel<8>,
            (const float*)pattn, opw, (float*)nullptr, ppart, (int)E, (int)E);
        pdl(dim3(NTOK), dim3(256), reduce_ln_kernel,
            (const float*)ppart, px, n2w + (size_t)i * E, n2b + (size_t)i * E, pxn);

        // l1: K=1024, N=4096, split-K=2 -> 128 blocks; gelu in reduce
        pdl(dim3(FF / 64, 2), dim3(256), gemv_kernel<2>,
            (const float*)pxn, l1, (float*)nullptr, ppart, (int)E, (int)FF);
        pdl(dim3((32 * FF + 255) / 256), dim3(256), reduce_gelu_kernel<2>,
            (const float*)ppart, ph, (int)FF);

        // l2: K=4096, N=1024, split-K=8 -> 128 blocks; fused reduce+add+LN/eos
        pdl(dim3(E / 64, 8), dim3(256), gemv_kernel<8>,
            (const float*)ph, l2, (float*)nullptr, ppart, (int)FF, (int)E);
        if (i + 1 < NL) {
            pdl(dim3(NTOK), dim3(256), reduce_ln_kernel,
                (const float*)ppart, px,
                n1w + (size_t)(i + 1) * E, n1b + (size_t)(i + 1) * E, pxn);
        } else {
            pdl(dim3(NTOK), dim3(256), reduce_ln_eos_kernel,
                (const float*)ppart, px, on_w, on_b, eos_w, eos_b,
                out_x, out_eos);
        }
    }
}